// round 12
// baseline (speedup 1.0000x reference)
#include <cuda_runtime.h>
#include <math.h>

// Problem constants
#define CC      50
#define HID     64
#define NB      10
#define NPATHS  5
#define NLAYERS 6
#define BB      64
#define LL      514
#define TT      512
#define NT      (BB*TT)
#define MAXR    0.06f
#define HALFBAR 0.05f
#define PI_F    3.14159265358979f

// wi(r) interpolation table
#define TKNOTS  256
#define TROWS   260

// Kernel config: 4 warps/block, 4 triplets per warp (2 t-pairs), 3 blocks/SM
#define TRIPW    4
#define WPB      4
#define NTHREADS 128
#define TPB      (WPB*TRIPW)      // 16
#define NBLOCKS  (NT/TPB)         // 2048

// Shared memory layout (float offsets)
#define WSS_OFF    0
#define WGS_OFF    2600
#define WVS_OFF    5200
#define OFF_HVT    7800
// hb per warp: 2 t-pairs, each 12 rows * 104 ([c][t] packed, 52 c incl pads)
#define HB_ROW     104
#define HB_TP      (12*HB_ROW)    // 1248
#define HB_WARP    (2*HB_TP)      // 2496
#define SMEM_FLOATS (OFF_HVT + WPB*HB_WARP)   // 17784
#define SMEM_BYTES  (SMEM_FLOATS*4)           // 71136

typedef unsigned long long u64;

__device__ float g_s1[NLAYERS][CC];
__device__ float g_wbar[NLAYERS][NPATHS*CC];
__device__ float g_witab[NLAYERS][TROWS][100];
__device__ float g_dummy;

__device__ __forceinline__ float siluf(float x){ return x/(1.f+__expf(-x)); }
__device__ __forceinline__ float sigmf(float x){ return 1.f/(1.f+__expf(-x)); }
__device__ __forceinline__ u64 fma2(u64 a, u64 b, u64 c){
    u64 d; asm("fma.rn.f32x2 %0, %1, %2, %3;" : "=l"(d) : "l"(a), "l"(b), "l"(c));
    return d;
}
__device__ __forceinline__ float2 unpack2(u64 a){
    float2 r; asm("mov.b64 {%0,%1}, %2;" : "=f"(r.x), "=f"(r.y) : "l"(a));
    return r;
}
__device__ __forceinline__ u64 swap64(u64 a){
    u64 d;
    asm("{\n\t.reg .b32 lo, hi;\n\tmov.b64 {lo,hi}, %1;\n\tmov.b64 %0, {hi,lo};\n\t}"
        : "=l"(d) : "l"(a));
    return d;
}

// ---------------------------------------------------------------------------
// One-launch precompute (table blocks + one serial-s1 block).
// ---------------------------------------------------------------------------
__global__ void e3nn_precompute(const float* __restrict__ Wr1,
                                const float* __restrict__ br1,
                                const float* __restrict__ Wr2,
                                const float* __restrict__ W_embed,
                                const float* __restrict__ Ws)
{
    const int tid = threadIdx.x;
    if (blockIdx.x == NLAYERS*(TROWS+1)) {
        __shared__ float s1[CC];
        float pf = 0.f;
        for (int i = tid; i < NLAYERS*CC*CC; i += 128) pf += Ws[i];   // L2 warm
        if (pf == 1.2345e30f) g_dummy = pf;
        if (tid < CC) s1[tid] = W_embed[tid] + W_embed[CC + tid];
        __syncthreads();
        for (int l = 0; l < NLAYERS; l++) {
            float acc = 0.f;
            if (tid < CC) {
                g_s1[l][tid] = s1[tid];
                #pragma unroll 5
                for (int c = 0; c < CC; c++) acc += s1[c]*Ws[(l*CC + c)*CC + tid];
            }
            __syncthreads();
            if (tid < CC) s1[tid] = siluf(acc);
            __syncthreads();
        }
        return;
    }
    const int l   = blockIdx.x / (TROWS+1);
    const int row = blockIdx.x - l*(TROWS+1);
    const bool intra = (row == TROWS);
    float r;
    if (intra) r = HALFBAR;
    else {
        int knot = row - 1;
        knot = knot < 0 ? 0 : (knot > TKNOTS ? TKNOTS : knot);
        r = (float)knot * (MAXR/(float)TKNOTS);
    }
    __shared__ float emb[NB+2], hid[HID], fcs;
    if (tid == 0) {
        float tt = fminf(fmaxf(r/MAXR, 0.f), 1.f);
        float fc = 0.5f*(cosf(PI_F*tt) + 1.f);
        fcs = fc;
        const float width = MAXR/(float)(NB-1);
        for (int i = 0; i < NB; i++) {
            float ci = MAXR*(float)i/(float)(NB-1);
            float d  = (r - ci)/width;
            emb[i]   = __expf(-d*d)*fc;
        }
        emb[NB]   = intra ? 0.f : 1.f;
        emb[NB+1] = intra ? 1.f : 0.f;
    }
    __syncthreads();
    if (tid < HID) {
        float acc = br1[l*HID + tid];
        #pragma unroll
        for (int i = 0; i < NB+2; i++) acc += emb[i]*Wr1[(l*(NB+2)+i)*HID + tid];
        hid[tid] = siluf(acc);
    }
    __syncthreads();
    if (intra) {
        for (int ch = tid; ch < NPATHS*CC; ch += 128) {
            float acc = 0.f;
            for (int j = 0; j < HID; j++)
                acc += hid[j]*Wr2[(l*HID + j)*(NPATHS*CC) + ch];
            g_wbar[l][ch] = acc*fcs;
        }
    } else if (tid < 100) {
        int k = tid >> 2, sub = tid & 3;
        int ch = (sub < 2) ? (2*k + sub) : (50 + 2*k + (sub-2));
        float acc = 0.f;
        for (int j = 0; j < HID; j++)
            acc += hid[j]*Wr2[(l*HID + j)*(NPATHS*CC) + ch];
        g_witab[l][row][tid] = acc*fcs;
    }
}

// ---------------------------------------------------------------------------
// Main fused kernel: t-pair hb, f32x2 GEMM, two-pass (S/G then V).
// ---------------------------------------------------------------------------
__global__ void __launch_bounds__(NTHREADS, 3) e3nn_main(
    const float* __restrict__ y,
    const float* __restrict__ W_embed,
    const float* __restrict__ Ws,
    const float* __restrict__ Wv,
    const float* __restrict__ Wg,
    const float* __restrict__ W_out,
    float* __restrict__ outp)
{
    extern __shared__ float sm[];
    const int tid  = threadIdx.x;
    const int w    = tid >> 5;
    const int lane = tid & 31;
    const int k    = lane;
    const bool act = (k < 25);
    const int c0   = 2*k;
    const int c1   = c0 + 1;

    const int gbase = blockIdx.x*TPB + w*TRIPW;
    float* hbW = sm + OFF_HVT + w*HB_WARP;

    // zero whole hb region once (pads at c-index 50,51 stay 0 forever)
    for (int i = tid; i < WPB*HB_WARP; i += NTHREADS) sm[OFF_HVT + i] = 0.f;

    // ---- geometry init ----
    float myUIx=0.f, myUIy=0.f, myU3x=0.f, myU3y=0.f, myR=1e9f;
    if (lane < TRIPW) {
        int g = gbase + lane;
        int b = g >> 9;
        int t = g & 511;
        const float* yb = y + ((size_t)b*LL + t)*6;
        float p0x = yb[0],  p0y = yb[1];
        float p1x = yb[6],  p1y = yb[7];
        float a   = yb[8];
        float ex = p0x - p1x, ey = p0y - p1y;
        float r  = sqrtf(ex*ex + ey*ey);
        float inv = 1.f/(r + 1e-12f);
        myUIx = ex*inv; myUIy = ey*inv;
        myU3x = sinf(a); myU3y = -cosf(a);
        myR = r;
    }
    float uIx[TRIPW], uIy[TRIPW], u3x[TRIPW], u3y[TRIPW], rT[TRIPW];
    #pragma unroll
    for (int t = 0; t < TRIPW; t++) {
        uIx[t] = __shfl_sync(0xffffffffu, myUIx, t);
        uIy[t] = __shfl_sync(0xffffffffu, myUIy, t);
        u3x[t] = __shfl_sync(0xffffffffu, myU3x, t);
        u3y[t] = __shfl_sync(0xffffffffu, myU3y, t);
        rT[t]  = __shfl_sync(0xffffffffu, myR,  t);
    }

    // ---- register state ----
    float s[TRIPW][3][2];
    float v[TRIPW][3][2][3];
    #pragma unroll
    for (int t = 0; t < TRIPW; t++)
        #pragma unroll
        for (int n = 0; n < 3; n++)
            #pragma unroll
            for (int q = 0; q < 2; q++) {
                s[t][n][q] = 0.f;
                v[t][n][q][0] = v[t][n][q][1] = v[t][n][q][2] = 0.f;
            }
    if (act) {
        float e00 = W_embed[c0],      e01 = W_embed[c1];
        float e10 = W_embed[CC+c0],   e11 = W_embed[CC+c1];
        float e20 = W_embed[2*CC+c0], e21 = W_embed[2*CC+c1];
        #pragma unroll
        for (int t = 0; t < TRIPW; t++) {
            s[t][0][0] = e00 + e20;  s[t][0][1] = e01 + e21;
            s[t][1][0] = e00 + e10;  s[t][1][1] = e01 + e11;
            s[t][2][0] = e00 + e20;  s[t][2][1] = e01 + e21;
        }
    }

    for (int l = 0; l < NLAYERS; l++) {
        __syncthreads();   // prior GEMM done reading weight buf (l=0: hb zeroed)
        // ---- stage Ws/Wg/Wv (contiguous float4) + zero pad rows 50,51 ----
        {
            const float4* sa = (const float4*)(Ws + (size_t)l*CC*CC);
            const float4* sb = (const float4*)(Wg + (size_t)l*CC*CC);
            const float4* sc = (const float4*)(Wv + (size_t)l*CC*CC);
            float4* da = (float4*)(sm + WSS_OFF);
            float4* db = (float4*)(sm + WGS_OFF);
            float4* dc = (float4*)(sm + WVS_OFF);
            for (int i = tid; i < 625; i += NTHREADS) { da[i]=sa[i]; db[i]=sb[i]; dc[i]=sc[i]; }
            for (int i = tid; i < 100; i += NTHREADS) {
                sm[WSS_OFF + 2500 + i] = 0.f;
                sm[WGS_OFF + 2500 + i] = 0.f;
                sm[WVS_OFF + 2500 + i] = 0.f;
            }
        }
        // ---- inter-edge weights via Catmull-Rom table ----
        float wi[TRIPW][4];
        if (act) {
            #pragma unroll
            for (int t = 0; t < TRIPW; t++) {
                float xr = rT[t]*((float)TKNOTS/MAXR);
                float valid = (xr < (float)TKNOTS) ? 1.f : 0.f;
                xr = fminf(xr, (float)TKNOTS - 0.001f);
                float jf = floorf(xr);
                int j = (int)jf;
                float u = xr - jf;
                float u2 = u*u, u3 = u2*u;
                float cw0 = 0.5f*(-u + 2.f*u2 - u3);
                float cw1 = 0.5f*(2.f - 5.f*u2 + 3.f*u3);
                float cw2 = 0.5f*(u + 4.f*u2 - 3.f*u3);
                float cw3 = 0.5f*(-u2 + u3);
                const float* tb = &g_witab[l][j][4*k];
                float4 r0 = *(const float4*)(tb);
                float4 r1 = *(const float4*)(tb + 100);
                float4 r2 = *(const float4*)(tb + 200);
                float4 r3 = *(const float4*)(tb + 300);
                wi[t][0] = valid*(cw0*r0.x + cw1*r1.x + cw2*r2.x + cw3*r3.x);
                wi[t][1] = valid*(cw0*r0.y + cw1*r1.y + cw2*r2.y + cw3*r3.y);
                wi[t][2] = valid*(cw0*r0.z + cw1*r1.z + cw2*r2.z + cw3*r3.z);
                wi[t][3] = valid*(cw0*r0.w + cw1*r1.w + cw2*r2.w + cw3*r3.w);
            }
        }
        // ---- messages -> hb, t-pair packed, float4 stores ----
        if (act) {
            float wb0[2], wb1[2], wb2[2], wb3[2], wb4[2], s1v[2];
            #pragma unroll
            for (int q = 0; q < 2; q++) {
                int cq = c0 + q;
                wb0[q] = g_wbar[l][cq];
                wb1[q] = g_wbar[l][50+cq];
                wb2[q] = g_wbar[l][100+cq];
                wb3[q] = g_wbar[l][150+cq];
                wb4[q] = g_wbar[l][200+cq];
                s1v[q] = g_s1[l][cq];
            }
            const int ce = 4*k;
            #pragma unroll
            for (int tp = 0; tp < 2; tp++) {
                float* hb = hbW + tp*HB_TP;
                float H3[2][2], H4[2][2], H5[2][2];
                float V3[2][2][3], V4[2][2][3], V5[2][2][3];
                #pragma unroll
                for (int q = 0; q < 2; q++) {
                    #pragma unroll
                    for (int j = 0; j < 2; j++) {
                        const int t = 2*tp + j;
                        float ux = u3x[t], uy = u3y[t];
                        float s4  = s[t][1][q];
                        float v4x = v[t][1][q][0], v4y = v[t][1][q][1], v4z = v[t][1][q][2];
                        H4[q][j] = s4 + wi[t][q]*s1v[q];
                        float w1i = wi[t][2+q]*s1v[q];
                        V4[q][j][0] = v4x + w1i*uIx[t];
                        V4[q][j][1] = v4y + w1i*uIy[t];
                        V4[q][j][2] = v4z;
                        float dotc = v4x*ux + v4y*uy;
                        float base = wb0[q]*s4;
                        H3[q][j] = s[t][0][q] + base + wb2[q]*dotc;
                        H5[q][j] = s[t][2][q] + base - wb2[q]*dotc;
                        float cx = -v4z*uy, cy = v4z*ux, cz = v4x*uy - v4y*ux;
                        float y2x = dotc*ux - v4x*(1.f/3.f);
                        float y2y = dotc*uy - v4y*(1.f/3.f);
                        float y2z = -v4z*(1.f/3.f);
                        float sx = wb1[q]*s4;
                        V3[q][j][0] = v[t][0][q][0] + sx*ux + wb3[q]*cx + wb4[q]*y2x;
                        V3[q][j][1] = v[t][0][q][1] + sx*uy + wb3[q]*cy + wb4[q]*y2y;
                        V3[q][j][2] = v[t][0][q][2]         + wb3[q]*cz + wb4[q]*y2z;
                        V5[q][j][0] = v[t][2][q][0] - sx*ux - wb3[q]*cx + wb4[q]*y2x;
                        V5[q][j][1] = v[t][2][q][1] - sx*uy - wb3[q]*cy + wb4[q]*y2y;
                        V5[q][j][2] = v[t][2][q][2]         - wb3[q]*cz + wb4[q]*y2z;
                    }
                }
                *(float4*)&hb[0*HB_ROW + ce] = make_float4(H3[0][0], H3[0][1], H3[1][0], H3[1][1]);
                *(float4*)&hb[1*HB_ROW + ce] = make_float4(H4[0][0], H4[0][1], H4[1][0], H4[1][1]);
                *(float4*)&hb[2*HB_ROW + ce] = make_float4(H5[0][0], H5[0][1], H5[1][0], H5[1][1]);
                #pragma unroll
                for (int d = 0; d < 3; d++) {
                    *(float4*)&hb[(3 + 0*3 + d)*HB_ROW + ce] = make_float4(V3[0][0][d], V3[0][1][d], V3[1][0][d], V3[1][1][d]);
                    *(float4*)&hb[(3 + 1*3 + d)*HB_ROW + ce] = make_float4(V4[0][0][d], V4[0][1][d], V4[1][0][d], V4[1][1][d]);
                    *(float4*)&hb[(3 + 2*3 + d)*HB_ROW + ce] = make_float4(V5[0][0][d], V5[0][1][d], V5[1][0][d], V5[1][1][d]);
                }
            }
        }
        __syncthreads();   // weights staged + hb written
        if (act) {
            float gt[3][2][4];   // [n][tp][g00,g01,g11,g10]
            // ---- Pass 1: S and G for all 3 nodes, weights loaded once/group ----
            {
                u64 DS[3][2], XS[3][2], DG[3][2], XG[3][2];
                #pragma unroll
                for (int n = 0; n < 3; n++)
                    #pragma unroll
                    for (int tp = 0; tp < 2; tp++) {
                        DS[n][tp]=XS[n][tp]=DG[n][tp]=XG[n][tp]=0ull;
                    }
                #pragma unroll 1
                for (int cg = 0; cg < 52; cg += 4) {
                    u64 wsp[4], wgp[4], wss[4], wgs[4];
                    #pragma unroll
                    for (int i = 0; i < 4; i++) {
                        wsp[i] = *(const u64*)&sm[WSS_OFF + (cg+i)*CC + c0];
                        wgp[i] = *(const u64*)&sm[WGS_OFF + (cg+i)*CC + c0];
                        wss[i] = swap64(wsp[i]);
                        wgs[i] = swap64(wgp[i]);
                    }
                    #pragma unroll
                    for (int tp = 0; tp < 2; tp++) {
                        const float* hb = hbW + tp*HB_TP;
                        #pragma unroll
                        for (int n = 0; n < 3; n++) {
                            ulonglong2 hA = *(const ulonglong2*)&hb[n*HB_ROW + cg*2];
                            ulonglong2 hB = *(const ulonglong2*)&hb[n*HB_ROW + cg*2 + 4];
                            u64 hu[4] = {hA.x, hA.y, hB.x, hB.y};
                            #pragma unroll
                            for (int i = 0; i < 4; i++) {
                                DS[n][tp] = fma2(hu[i], wsp[i], DS[n][tp]);
                                XS[n][tp] = fma2(hu[i], wss[i], XS[n][tp]);
                                DG[n][tp] = fma2(hu[i], wgp[i], DG[n][tp]);
                                XG[n][tp] = fma2(hu[i], wgs[i], XG[n][tp]);
                            }
                        }
                    }
                }
                #pragma unroll
                for (int n = 0; n < 3; n++)
                    #pragma unroll
                    for (int tp = 0; tp < 2; tp++) {
                        const int t0 = 2*tp, t1 = 2*tp + 1;
                        float2 ds = unpack2(DS[n][tp]), xs = unpack2(XS[n][tp]);
                        float2 dg = unpack2(DG[n][tp]), xg = unpack2(XG[n][tp]);
                        s[t0][n][0] = siluf(ds.x);  s[t0][n][1] = siluf(xs.x);
                        s[t1][n][1] = siluf(ds.y);  s[t1][n][0] = siluf(xs.y);
                        gt[n][tp][0] = sigmf(dg.x);
                        gt[n][tp][1] = sigmf(xg.x);
                        gt[n][tp][2] = sigmf(dg.y);
                        gt[n][tp][3] = sigmf(xg.y);
                    }
            }
            // ---- Pass 2: V per node ----
            #pragma unroll 1
            for (int n = 0; n < 3; n++) {
                u64 DV[3][2], XV[3][2];
                #pragma unroll
                for (int d = 0; d < 3; d++)
                    #pragma unroll
                    for (int tp = 0; tp < 2; tp++) { DV[d][tp]=XV[d][tp]=0ull; }
                #pragma unroll 1
                for (int cg = 0; cg < 52; cg += 4) {
                    u64 wvp[4], wvs[4];
                    #pragma unroll
                    for (int i = 0; i < 4; i++) {
                        wvp[i] = *(const u64*)&sm[WVS_OFF + (cg+i)*CC + c0];
                        wvs[i] = swap64(wvp[i]);
                    }
                    #pragma unroll
                    for (int tp = 0; tp < 2; tp++) {
                        const float* hb = hbW + tp*HB_TP;
                        ulonglong2 xA = *(const ulonglong2*)&hb[(3+n*3+0)*HB_ROW + cg*2];
                        ulonglong2 xB = *(const ulonglong2*)&hb[(3+n*3+0)*HB_ROW + cg*2 + 4];
                        ulonglong2 yA = *(const ulonglong2*)&hb[(3+n*3+1)*HB_ROW + cg*2];
                        ulonglong2 yB = *(const ulonglong2*)&hb[(3+n*3+1)*HB_ROW + cg*2 + 4];
                        ulonglong2 zA = *(const ulonglong2*)&hb[(3+n*3+2)*HB_ROW + cg*2];
                        ulonglong2 zB = *(const ulonglong2*)&hb[(3+n*3+2)*HB_ROW + cg*2 + 4];
                        u64 xu[4] = {xA.x, xA.y, xB.x, xB.y};
                        u64 yu[4] = {yA.x, yA.y, yB.x, yB.y};
                        u64 zu[4] = {zA.x, zA.y, zB.x, zB.y};
                        #pragma unroll
                        for (int i = 0; i < 4; i++) {
                            DV[0][tp] = fma2(xu[i], wvp[i], DV[0][tp]);
                            XV[0][tp] = fma2(xu[i], wvs[i], XV[0][tp]);
                            DV[1][tp] = fma2(yu[i], wvp[i], DV[1][tp]);
                            XV[1][tp] = fma2(yu[i], wvs[i], XV[1][tp]);
                            DV[2][tp] = fma2(zu[i], wvp[i], DV[2][tp]);
                            XV[2][tp] = fma2(zu[i], wvs[i], XV[2][tp]);
                        }
                    }
                }
                #pragma unroll
                for (int tp = 0; tp < 2; tp++) {
                    const int t0 = 2*tp, t1 = 2*tp + 1;
                    float g00 = gt[n][tp][0], g01 = gt[n][tp][1];
                    float g11 = gt[n][tp][2], g10 = gt[n][tp][3];
                    #pragma unroll
                    for (int d = 0; d < 3; d++) {
                        float2 dv = unpack2(DV[d][tp]), xv = unpack2(XV[d][tp]);
                        v[t0][n][0][d] = dv.x*g00;  v[t0][n][1][d] = xv.x*g01;
                        v[t1][n][1][d] = dv.y*g11;  v[t1][n][0][d] = xv.y*g10;
                    }
                }
            }
        }
    }

    // ---- epilogue ----
    float p[TRIPW][9];
    #pragma unroll
    for (int t = 0; t < TRIPW; t++)
        #pragma unroll
        for (int i = 0; i < 9; i++) p[t][i] = 0.f;
    if (act) {
        #pragma unroll
        for (int q = 0; q < 2; q++) {
            float wo = W_out[c0+q];
            #pragma unroll
            for (int t = 0; t < TRIPW; t++)
                #pragma unroll
                for (int n = 0; n < 3; n++)
                    #pragma unroll
                    for (int d = 0; d < 3; d++)
                        p[t][n*3+d] += wo*v[t][n][q][d];
        }
    }
    #pragma unroll
    for (int off = 16; off > 0; off >>= 1)
        #pragma unroll
        for (int t = 0; t < TRIPW; t++)
            #pragma unroll
            for (int i = 0; i < 9; i++)
                p[t][i] += __shfl_xor_sync(0xffffffffu, p[t][i], off);
    if (lane == 0) {
        #pragma unroll
        for (int t = 0; t < TRIPW; t++) {
            int g = gbase + t;
            int b = g >> 9;
            int tt = g & 511;
            float rx = p[t][0] + p[t][3] + p[t][6];
            float ry = p[t][1] + p[t][4] + p[t][7];
            float offx = -HALFBAR*u3x[t], offy = -HALFBAR*u3y[t];
            float rz = (offx*p[t][1] - offy*p[t][0]) - (offx*p[t][7] - offy*p[t][6]);
            float* o = outp + ((size_t)b*LL + (tt+1))*3;
            o[0] = rx; o[1] = ry; o[2] = rz;
        }
    }
}

// ---------------------------------------------------------------------------
extern "C" void kernel_launch(void* const* d_in, const int* in_sizes, int n_in,
                              void* d_out, int out_size)
{
    const float* y       = (const float*)d_in[0];
    const float* W_embed = (const float*)d_in[1];
    const float* Wr1     = (const float*)d_in[2];
    const float* br1     = (const float*)d_in[3];
    const float* Wr2     = (const float*)d_in[4];
    const float* Ws      = (const float*)d_in[5];
    const float* Wv      = (const float*)d_in[6];
    const float* Wg      = (const float*)d_in[7];
    const float* W_out   = (const float*)d_in[8];
    float* outp = (float*)d_out;

    cudaFuncSetAttribute(e3nn_main, cudaFuncAttributeMaxDynamicSharedMemorySize, SMEM_BYTES);

    cudaMemsetAsync(d_out, 0, (size_t)out_size*sizeof(float), 0);
    e3nn_precompute<<<NLAYERS*(TROWS+1) + 1, 128>>>(Wr1, br1, Wr2, W_embed, Ws);
    e3nn_main<<<NBLOCKS, NTHREADS, SMEM_BYTES>>>(y, W_embed, Ws, Wv, Wg, W_out, outp);
}